// round 14
// baseline (speedup 1.0000x reference)
#include <cuda_runtime.h>

#define BB 16
#define LL 200
#define HH 64
#define NHEAD 2
#define PREP_ROWS 16   // (b,l) rows per prep block

__device__ float g_Qp[BB * LL * HH];
__device__ float g_KpK[BB * LL * HH];
__device__ float g_VpV[BB * LL * HH];
__device__ int   g_mask_is_u8;   // 1 if masks stored as uint8, 0 if int32

__device__ __forceinline__ bool read_mask(const void* p, int i, int is_u8)
{
    return is_u8 ? (((const unsigned char*)p)[i] != 0)
                 : (((const int*)p)[i] != 0);
}

// ---------------------------------------------------------------------------
// Prep (register-blocked, ~2us). Block 0 also detects mask storage dtype.
// ---------------------------------------------------------------------------
__global__ __launch_bounds__(256) void prep_kernel(
    const float* __restrict__ queries, const float* __restrict__ keys,
    const float* __restrict__ abs_pos_K, const float* __restrict__ abs_pos_V,
    const float* __restrict__ Wq, const float* __restrict__ bq,
    const float* __restrict__ Wk, const float* __restrict__ bk,
    const float* __restrict__ Wv, const float* __restrict__ bv,
    const unsigned int* __restrict__ am_words)
{
    const int t = threadIdx.x;

    if (blockIdx.x == 0 && t < 64) {
        unsigned int bad = 0;
        for (int i = t; i < 256; i += 64) bad |= (am_words[i] > 1u);
        unsigned int any = __ballot_sync(0xffffffffu, bad != 0);
        if (t == 0) g_mask_is_u8 = (any != 0) ? 1 : 0;
    }

    __shared__ float  Wqs[HH][HH + 1];
    __shared__ float  Wks[HH][HH + 1];
    __shared__ float  Wvs[HH][HH + 1];
    __shared__ float4 xq4[PREP_ROWS][16];
    __shared__ float4 xk4[PREP_ROWS][16];

#pragma unroll
    for (int i = 0; i < 16; ++i) {
        int idx = i * 256 + t;
        int r = idx >> 6, c = idx & 63;
        Wqs[r][c] = Wq[idx];
        Wks[r][c] = Wk[idx];
        Wvs[r][c] = Wv[idx];
    }

    const int base_row = blockIdx.x * PREP_ROWS;
    {
        int r = t >> 4, j4 = t & 15;
        xq4[r][j4] = ((const float4*)queries)[(base_row + r) * 16 + j4];
        xk4[r][j4] = ((const float4*)keys)[(base_row + r) * 16 + j4];
    }
    __syncthreads();

    const int c = t & 63;
    const int g = t >> 6;

    float accq[4] = {0.f, 0.f, 0.f, 0.f};
    float acck[4] = {0.f, 0.f, 0.f, 0.f};
    float accv[4] = {0.f, 0.f, 0.f, 0.f};

#pragma unroll
    for (int j4 = 0; j4 < 16; ++j4) {
        const float wq0 = Wqs[c][4 * j4 + 0], wq1 = Wqs[c][4 * j4 + 1];
        const float wq2 = Wqs[c][4 * j4 + 2], wq3 = Wqs[c][4 * j4 + 3];
        const float wk0 = Wks[c][4 * j4 + 0], wk1 = Wks[c][4 * j4 + 1];
        const float wk2 = Wks[c][4 * j4 + 2], wk3 = Wks[c][4 * j4 + 3];
        const float wv0 = Wvs[c][4 * j4 + 0], wv1 = Wvs[c][4 * j4 + 1];
        const float wv2 = Wvs[c][4 * j4 + 2], wv3 = Wvs[c][4 * j4 + 3];
#pragma unroll
        for (int r = 0; r < 4; ++r) {
            const float4 xq = xq4[g * 4 + r][j4];
            const float4 xk = xk4[g * 4 + r][j4];
            accq[r] += xq.x * wq0 + xq.y * wq1 + xq.z * wq2 + xq.w * wq3;
            acck[r] += xk.x * wk0 + xk.y * wk1 + xk.z * wk2 + xk.w * wk3;
            accv[r] += xk.x * wv0 + xk.y * wv1 + xk.z * wv2 + xk.w * wv3;
        }
    }

#pragma unroll
    for (int r = 0; r < 4; ++r) {
        const int row = base_row + g * 4 + r;
        const int o   = row * HH + c;
        g_Qp[o]  = accq[r] + bq[c];
        g_KpK[o] = acck[r] + bk[c] + abs_pos_K[o];
        g_VpV[o] = accv[r] + bv[c] + abs_pos_V[o];
    }
}

// ---------------------------------------------------------------------------
// Streaming kernel for time-masked (uniform softmax) rows only:
// out[b,q,:] = (1/L) * sum_k (tV + dV + VpV). Pure sequential stream,
// minimal registers, no compaction/K-phase structure.
// ---------------------------------------------------------------------------
__global__ __launch_bounds__(256, 8) void uniform_kernel(
    const float* __restrict__ tV, const float* __restrict__ dV,
    const void* __restrict__ time_mask,
    float* __restrict__ out)
{
    const int bq = blockIdx.x;
    const int b  = bq / LL;
    const int t  = threadIdx.x;

    const bool tmq = read_mask(time_mask, bq, g_mask_is_u8);   // time_mask[b,q]
    if (!tmq) return;    // block-uniform: safe before barriers

    __shared__ float4 s_red[16][16];

    const int g    = t >> 4;
    const int idx4 = t & 15;

    const float4* tV4  = (const float4*)tV + (size_t)bq * LL * 16;
    const float4* dV4  = (const float4*)dV + (size_t)bq * LL * 16;
    const float4* VpV4 = (const float4*)g_VpV + b * LL * 16;

    float4 acc = make_float4(0.f, 0.f, 0.f, 0.f);
#pragma unroll 4
    for (int k = g; k < LL; k += 16) {
        const int o = k * 16 + idx4;
        float4 tv = __ldcs(tV4 + o);
        float4 dv = __ldcs(dV4 + o);
        float4 vp = VpV4[o];
        acc.x += tv.x + dv.x + vp.x;
        acc.y += tv.y + dv.y + vp.y;
        acc.z += tv.z + dv.z + vp.z;
        acc.w += tv.w + dv.w + vp.w;
    }
    s_red[g][idx4] = acc;
    __syncthreads();

    if (t < HH) {
        const int i4 = t >> 2;
        const int c  = t & 3;
        float sum = 0.f;
#pragma unroll
        for (int g2 = 0; g2 < 16; ++g2) {
            const float* v = (const float*)&s_red[g2][i4];
            sum += v[c];
        }
        out[bq * HH + t] = sum * (1.0f / LL);
    }
}

// ---------------------------------------------------------------------------
// Gather attention for non-time-masked rows (R9 loop bodies, 32 regs, 90%
// occ). tmq CTAs exit immediately; uniform_kernel covers them.
// ---------------------------------------------------------------------------
__global__ __launch_bounds__(256, 8) void attn_kernel(
    const float* __restrict__ tK, const float* __restrict__ dK,
    const float* __restrict__ tV, const float* __restrict__ dV,
    const void* __restrict__ time_mask,
    const void* __restrict__ attn_mask,
    float* __restrict__ out)
{
    const int bq = blockIdx.x;
    const int b  = bq / LL;
    const int q  = bq % LL;
    const int t    = threadIdx.x;
    const int warp = t >> 5;
    const int lane = t & 31;

    const int is_u8 = g_mask_is_u8;
    const bool tmq = read_mask(time_mask, bq, is_u8);
    if (tmq) return;     // block-uniform: safe before barriers

    __shared__ float s_p[NHEAD][LL];
    __shared__ float s_inv[NHEAD];
    __shared__ short s_idx[LL];
    __shared__ int   s_woff[8];
    __shared__ int   s_M;
    __shared__ float4 s_red[16][16];

    // ---- deterministic stream compaction of unmasked k ----
    {
        const int k = t;
        const bool valid = (k < LL) && !read_mask(attn_mask, q * LL + k, is_u8);
        const unsigned bal = __ballot_sync(0xffffffffu, valid);
        if (lane == 0) s_woff[warp] = __popc(bal);
        __syncthreads();
        if (t == 0) {
            int acc = 0;
#pragma unroll
            for (int w = 0; w < 8; ++w) { int c0 = s_woff[w]; s_woff[w] = acc; acc += c0; }
            s_M = acc;
        }
        __syncthreads();
        if (valid)
            s_idx[s_woff[warp] + __popc(bal & ((1u << lane) - 1u))] = (short)k;
    }
    __syncthreads();
    const int  M = s_M;
    const bool allmasked = (M == 0);      // ~2^-200 edge case: uniform weights

    const float scale = 0.17677669529663687f;   // 1/sqrt(32)

    // ---- K phase over compacted list ----
    if (!allmasked) {
        const int sub  = lane >> 4;
        const int idx4 = lane & 15;
        const int head = idx4 >> 3;

        const float4  q4   = ((const float4*)g_Qp + bq * 16)[idx4];
        const float4* tK4  = (const float4*)tK + (size_t)bq * LL * 16;
        const float4* dK4  = (const float4*)dK + (size_t)bq * LL * 16;
        const float4* KpK4 = (const float4*)g_KpK + b * LL * 16;

        for (int jb = warp * 2; jb < M; jb += 16) {   // warp-uniform bound
            const int  j   = jb + sub;
            const bool act = (j < M);
            const int  kk  = s_idx[act ? j : jb];
            const int  o   = kk * 16 + idx4;
            float4 tv = __ldcs(tK4 + o);
            float4 dv = __ldcs(dK4 + o);
            float4 kp = KpK4[o];
            float p = (tv.x + dv.x + kp.x) * q4.x
                    + (tv.y + dv.y + kp.y) * q4.y
                    + (tv.z + dv.z + kp.z) * q4.z
                    + (tv.w + dv.w + kp.w) * q4.w;
            p += __shfl_xor_sync(0xffffffffu, p, 1);
            p += __shfl_xor_sync(0xffffffffu, p, 2);
            p += __shfl_xor_sync(0xffffffffu, p, 4);
            if (act && (lane & 7) == 0) s_p[head][j] = p * scale;
        }
    }
    __syncthreads();

    // ---- softmax over compacted entries: warp h handles head h ----
    if (!allmasked && warp < NHEAD) {
        float m = -3.4e38f;
        for (int j = lane; j < M; j += 32) m = fmaxf(m, s_p[warp][j]);
#pragma unroll
        for (int s = 16; s > 0; s >>= 1)
            m = fmaxf(m, __shfl_xor_sync(0xffffffffu, m, s));
        float sum = 0.f;
        for (int j = lane; j < M; j += 32) {
            float e = __expf(s_p[warp][j] - m);
            s_p[warp][j] = e;
            sum += e;
        }
#pragma unroll
        for (int s = 16; s > 0; s >>= 1)
            sum += __shfl_xor_sync(0xffffffffu, sum, s);
        if (lane == 0) s_inv[warp] = 1.0f / sum;
    }
    __syncthreads();

    // ---- V phase ----
    {
        const int g    = t >> 4;
        const int idx4 = t & 15;
        const int head = idx4 >> 3;

        const float4* tV4  = (const float4*)tV + (size_t)bq * LL * 16;
        const float4* dV4  = (const float4*)dV + (size_t)bq * LL * 16;
        const float4* VpV4 = (const float4*)g_VpV + b * LL * 16;

        float4 acc = make_float4(0.f, 0.f, 0.f, 0.f);
        if (allmasked) {
#pragma unroll 4
            for (int k = g; k < LL; k += 16) {
                const int o = k * 16 + idx4;
                float4 tv = __ldcs(tV4 + o);
                float4 dv = __ldcs(dV4 + o);
                float4 vp = VpV4[o];
                acc.x += tv.x + dv.x + vp.x;
                acc.y += tv.y + dv.y + vp.y;
                acc.z += tv.z + dv.z + vp.z;
                acc.w += tv.w + dv.w + vp.w;
            }
        } else {
#pragma unroll 4
            for (int j = g; j < M; j += 16) {
                const int kk = s_idx[j];
                const float a = s_p[head][j];
                const int o = kk * 16 + idx4;
                float4 tv = __ldcs(tV4 + o);
                float4 dv = __ldcs(dV4 + o);
                float4 vp = VpV4[o];
                acc.x += a * (tv.x + dv.x + vp.x);
                acc.y += a * (tv.y + dv.y + vp.y);
                acc.z += a * (tv.z + dv.z + vp.z);
                acc.w += a * (tv.w + dv.w + vp.w);
            }
        }
        s_red[g][idx4] = acc;
    }
    __syncthreads();

    if (t < HH) {
        const int i4 = t >> 2;
        const int c  = t & 3;
        const float inv = allmasked ? (1.0f / LL) : s_inv[t >> 5];
        float sum = 0.f;
#pragma unroll
        for (int g2 = 0; g2 < 16; ++g2) {
            const float* v = (const float*)&s_red[g2][i4];
            sum += v[c];
        }
        out[bq * HH + t] = sum * inv;
    }
}

// ---------------------------------------------------------------------------
extern "C" void kernel_launch(void* const* d_in, const int* in_sizes, int n_in,
                              void* d_out, int out_size)
{
    const float* queries  = (const float*)d_in[0];
    const float* keys     = (const float*)d_in[1];
    const void*  time_mask = d_in[2];
    const void*  attn_mask = d_in[3];
    const float* tK = (const float*)d_in[4];
    const float* tV = (const float*)d_in[5];
    const float* dK = (const float*)d_in[6];
    const float* dV = (const float*)d_in[7];
    const float* abs_pos_K = (const float*)d_in[8];
    const float* abs_pos_V = (const float*)d_in[9];
    const float* Wq = (const float*)d_in[10];
    const float* bq = (const float*)d_in[11];
    const float* Wk = (const float*)d_in[12];
    const float* bk = (const float*)d_in[13];
    const float* Wv = (const float*)d_in[14];
    const float* bv = (const float*)d_in[15];
    float* out = (float*)d_out;

    prep_kernel<<<BB * LL / PREP_ROWS, 256>>>(queries, keys, abs_pos_K, abs_pos_V,
                                              Wq, bq, Wk, bk, Wv, bv,
                                              (const unsigned int*)attn_mask);
    uniform_kernel<<<BB * LL, 256>>>(tV, dV, time_mask, out);
    attn_kernel<<<BB * LL, 256>>>(tK, dK, tV, dV, time_mask, attn_mask, out);
}

// round 15
// speedup vs baseline: 1.1235x; 1.1235x over previous
#include <cuda_runtime.h>

#define BB 16
#define LL 200
#define HH 64
#define NHEAD 2
#define PREP_ROWS 8    // (b,l) rows per prep block (2 per thread)

__device__ float g_Qp[BB * LL * HH];
__device__ float g_KpK[BB * LL * HH];
__device__ float g_VpV[BB * LL * HH];
__device__ int   g_mask_is_u8;   // 1 if masks stored as uint8, 0 if int32

__device__ __forceinline__ bool read_mask(const void* p, int i, int is_u8)
{
    return is_u8 ? (((const unsigned char*)p)[i] != 0)
                 : (((const int*)p)[i] != 0);
}

// ---------------------------------------------------------------------------
// Prep: Qp = queries@Wq^T + bq ; KpK = keys@Wk^T + bk + abs_pos_K ;
//       VpV = keys@Wv^T + bv + abs_pos_V.
// 2 rows per thread (R14 profile: 4 rows -> 78 regs -> 16.7% occ, 9.4us).
// 400 blocks for better wave balance. Block 0 also detects mask dtype.
// ---------------------------------------------------------------------------
__global__ __launch_bounds__(256) void prep_kernel(
    const float* __restrict__ queries, const float* __restrict__ keys,
    const float* __restrict__ abs_pos_K, const float* __restrict__ abs_pos_V,
    const float* __restrict__ Wq, const float* __restrict__ bq,
    const float* __restrict__ Wk, const float* __restrict__ bk,
    const float* __restrict__ Wv, const float* __restrict__ bv,
    const unsigned int* __restrict__ am_words)
{
    const int t = threadIdx.x;

    if (blockIdx.x == 0 && t < 64) {
        // uint8 storage packs 4 random bools/word -> some word > 1 a.s.
        unsigned int bad = 0;
        for (int i = t; i < 256; i += 64) bad |= (am_words[i] > 1u);
        unsigned int any = __ballot_sync(0xffffffffu, bad != 0);
        if (t == 0) g_mask_is_u8 = (any != 0) ? 1 : 0;
    }

    __shared__ float  Wqs[HH][HH + 1];
    __shared__ float  Wks[HH][HH + 1];
    __shared__ float  Wvs[HH][HH + 1];
    __shared__ float4 xq4[PREP_ROWS][16];
    __shared__ float4 xk4[PREP_ROWS][16];

    // Coalesced cooperative load of the three 64x64 weight matrices.
#pragma unroll
    for (int i = 0; i < 16; ++i) {
        int idx = i * 256 + t;
        int r = idx >> 6, c = idx & 63;
        Wqs[r][c] = Wq[idx];
        Wks[r][c] = Wk[idx];
        Wvs[r][c] = Wv[idx];
    }

    const int base_row = blockIdx.x * PREP_ROWS;
    if (t < PREP_ROWS * 16) {
        int r = t >> 4, j4 = t & 15;
        xq4[r][j4] = ((const float4*)queries)[(base_row + r) * 16 + j4];
        xk4[r][j4] = ((const float4*)keys)[(base_row + r) * 16 + j4];
    }
    __syncthreads();

    const int c = t & 63;       // output column
    const int g = t >> 6;       // row group 0..3 -> rows g*2, g*2+1

    float accq[2] = {0.f, 0.f};
    float acck[2] = {0.f, 0.f};
    float accv[2] = {0.f, 0.f};

#pragma unroll
    for (int j4 = 0; j4 < 16; ++j4) {
        const float wq0 = Wqs[c][4 * j4 + 0], wq1 = Wqs[c][4 * j4 + 1];
        const float wq2 = Wqs[c][4 * j4 + 2], wq3 = Wqs[c][4 * j4 + 3];
        const float wk0 = Wks[c][4 * j4 + 0], wk1 = Wks[c][4 * j4 + 1];
        const float wk2 = Wks[c][4 * j4 + 2], wk3 = Wks[c][4 * j4 + 3];
        const float wv0 = Wvs[c][4 * j4 + 0], wv1 = Wvs[c][4 * j4 + 1];
        const float wv2 = Wvs[c][4 * j4 + 2], wv3 = Wvs[c][4 * j4 + 3];
#pragma unroll
        for (int r = 0; r < 2; ++r) {
            const float4 xq = xq4[g * 2 + r][j4];
            const float4 xk = xk4[g * 2 + r][j4];
            accq[r] += xq.x * wq0 + xq.y * wq1 + xq.z * wq2 + xq.w * wq3;
            acck[r] += xk.x * wk0 + xk.y * wk1 + xk.z * wk2 + xk.w * wk3;
            accv[r] += xk.x * wv0 + xk.y * wv1 + xk.z * wv2 + xk.w * wv3;
        }
    }

#pragma unroll
    for (int r = 0; r < 2; ++r) {
        const int row = base_row + g * 2 + r;
        const int o   = row * HH + c;
        g_Qp[o]  = accq[r] + bq[c];
        g_KpK[o] = acck[r] + bk[c] + abs_pos_K[o];
        g_VpV[o] = accv[r] + bv[c] + abs_pos_V[o];
    }
}

// ---------------------------------------------------------------------------
// Fused attention with mask-aware load skipping. (R9 exact: 32 regs, 90% occ,
// 73% DRAM, 57.1us — confirmed local optimum over R10-R14 experiments.)
// ---------------------------------------------------------------------------
__global__ __launch_bounds__(256, 8) void attn_kernel(
    const float* __restrict__ tK, const float* __restrict__ dK,
    const float* __restrict__ tV, const float* __restrict__ dV,
    const void* __restrict__ time_mask,
    const void* __restrict__ attn_mask,
    float* __restrict__ out)
{
    const int bq = blockIdx.x;
    const int b  = bq / LL;
    const int q  = bq % LL;
    const int t    = threadIdx.x;
    const int warp = t >> 5;
    const int lane = t & 31;

    __shared__ float s_p[NHEAD][LL];      // unnormalized probs at compacted idx
    __shared__ float s_inv[NHEAD];
    __shared__ short s_idx[LL];           // compacted unmasked k indices
    __shared__ int   s_woff[8];
    __shared__ int   s_M;
    __shared__ float4 s_red[16][16];

    const int is_u8 = g_mask_is_u8;
    const bool tmq = read_mask(time_mask, b * LL + q, is_u8);
    if (t == 0) s_M = 0;
    __syncthreads();

    // ---- deterministic stream compaction of unmasked k (skip if tmq) ----
    if (!tmq) {
        const int k = t;
        const bool valid = (k < LL) && !read_mask(attn_mask, q * LL + k, is_u8);
        const unsigned bal = __ballot_sync(0xffffffffu, valid);
        if (lane == 0) s_woff[warp] = __popc(bal);
        __syncthreads();
        if (t == 0) {
            int acc = 0;
#pragma unroll
            for (int w = 0; w < 8; ++w) { int c0 = s_woff[w]; s_woff[w] = acc; acc += c0; }
            s_M = acc;
        }
        __syncthreads();
        if (valid)
            s_idx[s_woff[warp] + __popc(bal & ((1u << lane) - 1u))] = (short)k;
    }
    __syncthreads();
    const int  M = s_M;
    const bool uniform = (M == 0);        // tmq rows or fully-masked rows

    const float scale = 0.17677669529663687f;   // 1/sqrt(32)

    // ---- K phase over compacted list (skipped when uniform) ----
    // Warp-uniform trip count; sub-half activity predicates only the smem
    // write, never the shuffles.
    if (!uniform) {
        const int sub  = lane >> 4;
        const int idx4 = lane & 15;
        const int head = idx4 >> 3;

        const float4  q4   = ((const float4*)g_Qp + bq * 16)[idx4];
        const float4* tK4  = (const float4*)tK + (size_t)bq * LL * 16;
        const float4* dK4  = (const float4*)dK + (size_t)bq * LL * 16;
        const float4* KpK4 = (const float4*)g_KpK + b * LL * 16;

        for (int jb = warp * 2; jb < M; jb += 16) {
            const int  j   = jb + sub;
            const bool act = (j < M);
            const int  jj  = act ? j : jb;          // safe duplicate index
            const int  kk  = s_idx[jj];
            const int  o   = kk * 16 + idx4;
            float4 tv = __ldcs(tK4 + o);
            float4 dv = __ldcs(dK4 + o);
            float4 kp = KpK4[o];
            float p = (tv.x + dv.x + kp.x) * q4.x
                    + (tv.y + dv.y + kp.y) * q4.y
                    + (tv.z + dv.z + kp.z) * q4.z
                    + (tv.w + dv.w + kp.w) * q4.w;
            p += __shfl_xor_sync(0xffffffffu, p, 1);
            p += __shfl_xor_sync(0xffffffffu, p, 2);
            p += __shfl_xor_sync(0xffffffffu, p, 4);
            if (act && (lane & 7) == 0) s_p[head][j] = p * scale;
        }
    }
    __syncthreads();

    // ---- softmax over compacted entries: warp h handles head h ----
    if (!uniform && warp < NHEAD) {
        float m = -3.4e38f;
        for (int j = lane; j < M; j += 32) m = fmaxf(m, s_p[warp][j]);
#pragma unroll
        for (int s = 16; s > 0; s >>= 1)
            m = fmaxf(m, __shfl_xor_sync(0xffffffffu, m, s));
        float sum = 0.f;
        for (int j = lane; j < M; j += 32) {
            float e = __expf(s_p[warp][j] - m);
            s_p[warp][j] = e;
            sum += e;
        }
#pragma unroll
        for (int s = 16; s > 0; s >>= 1)
            sum += __shfl_xor_sync(0xffffffffu, sum, s);
        if (lane == 0) s_inv[warp] = 1.0f / sum;
    }
    __syncthreads();

    // ---- V phase (no shuffles; divergence is safe) ----
    {
        const int g    = t >> 4;
        const int idx4 = t & 15;
        const int head = idx4 >> 3;

        const float4* tV4  = (const float4*)tV + (size_t)bq * LL * 16;
        const float4* dV4  = (const float4*)dV + (size_t)bq * LL * 16;
        const float4* VpV4 = (const float4*)g_VpV + b * LL * 16;

        float4 acc = make_float4(0.f, 0.f, 0.f, 0.f);
        if (uniform) {
#pragma unroll 4
            for (int k = g; k < LL; k += 16) {
                const int o = k * 16 + idx4;
                float4 tv = __ldcs(tV4 + o);
                float4 dv = __ldcs(dV4 + o);
                float4 vp = VpV4[o];
                acc.x += tv.x + dv.x + vp.x;
                acc.y += tv.y + dv.y + vp.y;
                acc.z += tv.z + dv.z + vp.z;
                acc.w += tv.w + dv.w + vp.w;
            }
        } else {
#pragma unroll 4
            for (int j = g; j < M; j += 16) {
                const int kk = s_idx[j];
                const float a = s_p[head][j];
                const int o = kk * 16 + idx4;
                float4 tv = __ldcs(tV4 + o);
                float4 dv = __ldcs(dV4 + o);
                float4 vp = VpV4[o];
                acc.x += a * (tv.x + dv.x + vp.x);
                acc.y += a * (tv.y + dv.y + vp.y);
                acc.z += a * (tv.z + dv.z + vp.z);
                acc.w += a * (tv.w + dv.w + vp.w);
            }
        }
        s_red[g][idx4] = acc;
    }
    __syncthreads();

    if (t < HH) {
        const int idx4 = t >> 2;
        const int c    = t & 3;
        const float inv = uniform ? (1.0f / LL) : s_inv[t >> 5];
        float sum = 0.f;
#pragma unroll
        for (int g = 0; g < 16; ++g) {
            const float* v = (const float*)&s_red[g][idx4];
            sum += v[c];
        }
        out[bq * HH + t] = sum * inv;
    }
}

// ---------------------------------------------------------------------------
extern "C" void kernel_launch(void* const* d_in, const int* in_sizes, int n_in,
                              void* d_out, int out_size)
{
    const float* queries  = (const float*)d_in[0];
    const float* keys     = (const float*)d_in[1];
    const void*  time_mask = d_in[2];
    const void*  attn_mask = d_in[3];
    const float* tK = (const float*)d_in[4];
    const float* tV = (const float*)d_in[5];
    const float* dK = (const float*)d_in[6];
    const float* dV = (const float*)d_in[7];
    const float* abs_pos_K = (const float*)d_in[8];
    const float* abs_pos_V = (const float*)d_in[9];
    const float* Wq = (const float*)d_in[10];
    const float* bq = (const float*)d_in[11];
    const float* Wk = (const float*)d_in[12];
    const float* bk = (const float*)d_in[13];
    const float* Wv = (const float*)d_in[14];
    const float* bv = (const float*)d_in[15];
    float* out = (float*)d_out;

    prep_kernel<<<BB * LL / PREP_ROWS, 256>>>(queries, keys, abs_pos_K, abs_pos_V,
                                              Wq, bq, Wk, bk, Wv, bv,
                                              (const unsigned int*)attn_mask);
    attn_kernel<<<BB * LL, 256>>>(tK, dK, tV, dV, time_mask, attn_mask, out);
}